// round 7
// baseline (speedup 1.0000x reference)
#include <cuda_runtime.h>
#include <cuda_fp16.h>
#include <cstdint>

#define B_   64
#define T_   512
#define H_   1024
#define L_   4
#define O_   256
#define NCTA 128
#define NTHR 256

#define KC      128                       // K per chunk
#define NCHUNK  16                        // 2048 / 128
#define WSTG    32768                     // W tile 128 rows x 256B
#define ASTG    16384                     // A tile  64 rows x 256B
#define STG     (WSTG + ASTG)             // 49152 per stage
#define OFF_SG  (3 * STG)                 // 147456 : gate preacts 64x128 f32
#define OFF_SC  (OFF_SG + 64 * 128 * 4)   // 180224 : cell state 64x32 f32
#define SMEM_TOTAL (OFF_SC + 8192)        // 188416

// XOR-swizzled index into sG: m in [0,64) batch, n in [0,128) gate col
#define SGIDX(m, n) (((m) << 7) + (((n) ^ (((m) & 7) << 1))))

// ---------------- scratch (static device globals; no allocation) ----------------
__device__ __half g_Wc[(size_t)L_ * 32 * 128 * 2048];  // [l][s][j=128][k=2048] fp16
__device__ __half g_x[(size_t)T_ * B_ * H_];           // x fp16, [t][b][d]
__device__ __half g_h[2 * L_ * B_ * H_];               // h fp16, [parity][l][b][h]
__device__ float  g_bias[L_ * 4 * H_];                 // bih + bhh
__device__ float  g_h3[B_ * H_];                       // final layer-3 h (fp32)
__device__ unsigned g_barGen;
__device__ unsigned g_barCnt;

// ---------------- helpers --------------------------------------------------------
__device__ __forceinline__ uint32_t smem_u32(const void* p) {
    uint32_t a;
    asm("{ .reg .u64 t; cvta.to.shared.u64 t, %1; cvt.u32.u64 %0, t; }" : "=r"(a) : "l"(p));
    return a;
}
__device__ __forceinline__ void cpa16(uint32_t dst, const void* src) {
    asm volatile("cp.async.cg.shared.global [%0], [%1], 16;" :: "r"(dst), "l"(src) : "memory");
}
__device__ __forceinline__ void cp_commit() {
    asm volatile("cp.async.commit_group;" ::: "memory");
}
__device__ __forceinline__ void cp_wait1() {
    asm volatile("cp.async.wait_group 1;" ::: "memory");
}
__device__ __forceinline__ void ldsm4(uint32_t* r, uint32_t a) {
    asm volatile("ldmatrix.sync.aligned.m8n8.x4.shared.b16 {%0,%1,%2,%3}, [%4];"
                 : "=r"(r[0]), "=r"(r[1]), "=r"(r[2]), "=r"(r[3]) : "r"(a));
}
__device__ __forceinline__ void mma16816(float* c, const uint32_t* a, const uint32_t* b) {
    asm volatile(
        "mma.sync.aligned.m16n8k16.row.col.f32.f16.f16.f32 "
        "{%0,%1,%2,%3}, {%4,%5,%6,%7}, {%8,%9}, {%0,%1,%2,%3};\n"
        : "+f"(c[0]), "+f"(c[1]), "+f"(c[2]), "+f"(c[3])
        : "r"(a[0]), "r"(a[1]), "r"(a[2]), "r"(a[3]), "r"(b[0]), "r"(b[1]));
}

// ---------------- grid barrier (128 CTAs, 1/SM, all resident) --------------------
__device__ __forceinline__ void gridBarrier() {
    __threadfence();
    __syncthreads();
    if (threadIdx.x == 0) {
        unsigned gen = *((volatile unsigned*)&g_barGen);
        __threadfence();
        unsigned prev = atomicAdd(&g_barCnt, 1u);
        if (prev == NCTA - 1) {
            g_barCnt = 0;
            __threadfence();
            atomicAdd(&g_barGen, 1u);
        } else {
            while (*((volatile unsigned*)&g_barGen) == gen) { }
        }
    }
    __syncthreads();
}

// ---------------- prep: weight swizzle + x fp16 + fused bias ---------------------
__global__ void prep_kernel(const float* __restrict__ x,
                            const float* __restrict__ Wih,
                            const float* __restrict__ Whh,
                            const float* __restrict__ bih,
                            const float* __restrict__ bhh) {
    long long tid = (long long)blockIdx.x * blockDim.x + threadIdx.x;
    long long stride = (long long)gridDim.x * blockDim.x;

    const long long NW = (long long)L_ * 32 * 128 * 2048;
    for (long long n = tid; n < NW; n += stride) {
        int k = (int)(n & 2047);
        int j = (int)((n >> 11) & 127);
        int s = (int)((n >> 18) & 31);
        int l = (int)(n >> 23);
        int g = j >> 5, jj = j & 31;
        int row = g * 1024 + s * 32 + jj;
        float v = (k < 1024)
            ? Wih[((long long)l * 4096 + row) * 1024 + k]
            : Whh[((long long)l * 4096 + row) * 1024 + (k - 1024)];
        g_Wc[n] = __float2half_rn(v);
    }

    const long long NX = (long long)T_ * B_ * H_;
    for (long long n = tid; n < NX; n += stride) {
        int d = (int)(n & 1023);
        int b = (int)((n >> 10) & 63);
        int t = (int)(n >> 16);
        g_x[n] = __float2half_rn(x[((long long)b * T_ + t) * H_ + d]);
    }

    for (long long n = tid; n < L_ * 4 * H_; n += stride)
        g_bias[n] = bih[n] + bhh[n];
}

// ---------------- persistent LSTM kernel -----------------------------------------
__global__ void __launch_bounds__(NTHR, 1) lstm_kernel() {
    extern __shared__ __align__(1024) char smem[];
    const uint32_t sb = smem_u32(smem);
    const int tid = threadIdx.x;
    const int lane = tid & 31;
    const int wid = tid >> 5;
    const int bid = blockIdx.x;
    const int l = bid >> 5;          // layer
    const int s = bid & 31;          // gate-column slice (32 h cols)

    float* sG = (float*)(smem + OFF_SG);  // [b=64][n=128] XOR-swizzled
    float* sC = (float*)(smem + OFF_SC);  // [b=64][hc=32]

    // zero h double buffer + c state
    {
        const int total = (2 * L_ * B_ * H_) / 8;     // uint4 count
        uint4 z = make_uint4(0, 0, 0, 0);
        for (int i = bid * NTHR + tid; i < total; i += NCTA * NTHR)
            ((uint4*)g_h)[i] = z;
        for (int i = tid; i < B_ * 32; i += NTHR) sC[i] = 0.f;
    }

    // elementwise constants
    const int hcl = tid & 31;
    const int eb0 = tid >> 5;
    float bias_g[4];
    #pragma unroll
    for (int g = 0; g < 4; ++g)
        bias_g[g] = g_bias[l * 4096 + g * 1024 + s * 32 + hcl];

    // warp decomposition: ks = K quarter (0..3), wn = gate half (0..1)
    const int ks = wid >> 1;
    const int wn = wid & 1;
    const int t8 = lane >> 3;
    const int r8 = lane & 7;
    const uint32_t swz = (uint32_t)r8;
    const uint32_t tA = (uint32_t)(t8 >> 1);
    const uint32_t tB = (uint32_t)(t8 & 1);

    // stage-independent byte offsets (stage base added in loop)
    uint32_t aOff[4], bOff[4];
    #pragma unroll
    for (int mi = 0; mi < 4; ++mi) {
        int m = mi * 16 + (t8 & 1) * 8 + r8;           // batch row
        aOff[mi] = (uint32_t)(WSTG + m * 256);
    }
    #pragma unroll
    for (int p = 0; p < 4; ++p) {
        int n = wn * 64 + p * 16 + (t8 >> 1) * 8 + r8; // gate row
        bOff[p] = (uint32_t)(n * 256);
    }

    const __half* Wbase = g_Wc + (size_t)(l * 32 + s) * 128 * 2048;

    gridBarrier();

    for (int tau = 0; tau < T_ + L_ - 1; ++tau) {
        const int t = tau - l;
        if (t >= 0 && t < T_) {
            const int par = tau & 1;
            const __half* hin = g_h + (par ^ 1) * (L_ * B_ * H_);
            const __half* in  = (l == 0) ? (g_x + (size_t)t * (B_ * H_))
                                         : (hin + (l - 1) * (B_ * H_));
            const __half* rec = hin + l * (B_ * H_);

            auto issueChunk = [&](int kc, int st) {
                const __half* Wsrc = Wbase + kc * KC;
                uint32_t wdst = sb + st * STG;
                #pragma unroll
                for (int q = 0; q < 8; ++q) {
                    int f = tid + q * 256;
                    int j = f >> 4, c16 = f & 15;
                    uint32_t d = wdst + (uint32_t)(j * 256) + ((uint32_t)(c16 ^ (j & 7)) << 4);
                    cpa16(d, Wsrc + (size_t)j * 2048 + c16 * 8);
                }
                const __half* Asrc = (kc < 8) ? in : rec;
                const int kloc = (kc & 7) * KC;
                uint32_t adst = wdst + WSTG;
                #pragma unroll
                for (int q = 0; q < 4; ++q) {
                    int f = tid + q * 256;
                    int b = f >> 4, c16 = f & 15;
                    uint32_t d = adst + (uint32_t)(b * 256) + ((uint32_t)(c16 ^ (b & 7)) << 4);
                    cpa16(d, Asrc + (size_t)b * 1024 + kloc + c16 * 8);
                }
            };

            float acc[4][8][4];
            #pragma unroll
            for (int mi = 0; mi < 4; ++mi)
                #pragma unroll
                for (int ni = 0; ni < 8; ++ni)
                    #pragma unroll
                    for (int q = 0; q < 4; ++q) acc[mi][ni][q] = 0.f;

            issueChunk(0, 0); cp_commit();
            issueChunk(1, 1); cp_commit();

            #pragma unroll
            for (int kc = 0; kc < NCHUNK; ++kc) {
                const int st = kc % 3;
                const uint32_t stBase = sb + st * STG;
                cp_wait1();            // chunk kc resident (this thread)
                __syncthreads();       // all threads' chunk kc resident
                if (kc + 2 < NCHUNK) issueChunk(kc + 2, (kc + 2) % 3);
                cp_commit();           // keeps group counts aligned

                #pragma unroll
                for (int j = 0; j < 2; ++j) {
                    const uint32_t kk = (uint32_t)(ks * 2 + j);
                    uint32_t a[4][4], bf[4][4];
                    #pragma unroll
                    for (int mi = 0; mi < 4; ++mi)
                        ldsm4(a[mi], stBase + aOff[mi] + (((2 * kk + tA) ^ swz) << 4));
                    #pragma unroll
                    for (int p = 0; p < 4; ++p)
                        ldsm4(bf[p], stBase + bOff[p] + (((2 * kk + tB) ^ swz) << 4));
                    #pragma unroll
                    for (int mi = 0; mi < 4; ++mi)
                        #pragma unroll
                        for (int p = 0; p < 4; ++p) {
                            mma16816(acc[mi][2 * p],     a[mi], &bf[p][0]);
                            mma16816(acc[mi][2 * p + 1], a[mi], &bf[p][2]);
                        }
                }
            }

            // ---- cross-warp K reduction into sG (4 rounds over k-quarters) ----
            {
                const int grp = lane >> 2, tg = lane & 3;
                #pragma unroll
                for (int r = 0; r < 4; ++r) {
                    if (ks == r) {
                        #pragma unroll
                        for (int mi = 0; mi < 4; ++mi)
                            #pragma unroll
                            for (int pq = 0; pq < 8; ++pq) {
                                int n = wn * 64 + (pq >> 1) * 16 + (pq & 1) * 8 + tg * 2;
                                int m0 = mi * 16 + grp;
                                const float* c = acc[mi][pq];
                                float2* d0 = (float2*)&sG[SGIDX(m0, n)];
                                float2* d1 = (float2*)&sG[SGIDX(m0 + 8, n)];
                                if (r == 0) {
                                    *d0 = make_float2(c[0], c[1]);
                                    *d1 = make_float2(c[2], c[3]);
                                } else {
                                    float2 v0 = *d0, v1 = *d1;
                                    v0.x += c[0]; v0.y += c[1];
                                    v1.x += c[2]; v1.y += c[3];
                                    *d0 = v0; *d1 = v1;
                                }
                            }
                    }
                    __syncthreads();
                }
            }

            // ---- elementwise LSTM cell ----
            __half* hout = g_h + par * (L_ * B_ * H_) + l * (B_ * H_);
            #pragma unroll
            for (int b = eb0; b < 64; b += 8) {
                float ai = sG[SGIDX(b, 0 * 32 + hcl)] + bias_g[0];
                float af = sG[SGIDX(b, 1 * 32 + hcl)] + bias_g[1];
                float ag = sG[SGIDX(b, 2 * 32 + hcl)] + bias_g[2];
                float ao = sG[SGIDX(b, 3 * 32 + hcl)] + bias_g[3];
                float ig = 1.f / (1.f + expf(-ai));
                float fg = 1.f / (1.f + expf(-af));
                float gg = tanhf(ag);
                float og = 1.f / (1.f + expf(-ao));
                float cs = fg * sC[b * 32 + hcl] + ig * gg;
                sC[b * 32 + hcl] = cs;
                float hv = og * tanhf(cs);
                int go = b * 1024 + s * 32 + hcl;
                __stcg(hout + go, __float2half_rn(hv));
                if (l == 3 && t == T_ - 1) g_h3[go] = hv;
            }
        }
        gridBarrier();
    }
}

// ---------------- final FC: out[b][o] = h3[b] . fc_w[o] + fc_b[o] ----------------
__global__ void fc_kernel(const float* __restrict__ fc_w,
                          const float* __restrict__ fc_b,
                          float* __restrict__ out) {
    __shared__ float hs[H_];
    const int b = blockIdx.x;
    const int o = threadIdx.x;
    for (int k = o; k < H_; k += O_) hs[k] = g_h3[b * H_ + k];
    __syncthreads();
    const float* w = fc_w + (long long)o * H_;
    float a0 = 0.f, a1 = 0.f, a2 = 0.f, a3 = 0.f;
    #pragma unroll 4
    for (int k = 0; k < H_; k += 4) {
        a0 += hs[k + 0] * __ldg(w + k + 0);
        a1 += hs[k + 1] * __ldg(w + k + 1);
        a2 += hs[k + 2] * __ldg(w + k + 2);
        a3 += hs[k + 3] * __ldg(w + k + 3);
    }
    out[b * O_ + o] = fc_b[o] + ((a0 + a1) + (a2 + a3));
}

// ---------------- launch ----------------------------------------------------------
extern "C" void kernel_launch(void* const* d_in, const int* in_sizes, int n_in,
                              void* d_out, int out_size) {
    (void)in_sizes; (void)n_in; (void)out_size;
    const float* x    = (const float*)d_in[0];
    const float* Wih  = (const float*)d_in[1];
    const float* Whh  = (const float*)d_in[2];
    const float* bih  = (const float*)d_in[3];
    const float* bhh  = (const float*)d_in[4];
    const float* fc_w = (const float*)d_in[5];
    const float* fc_b = (const float*)d_in[6];

    cudaFuncSetAttribute(lstm_kernel, cudaFuncAttributeMaxDynamicSharedMemorySize, SMEM_TOTAL);
    prep_kernel<<<2048, 256>>>(x, Wih, Whh, bih, bhh);
    lstm_kernel<<<NCTA, NTHR, SMEM_TOTAL>>>();
    fc_kernel<<<B_, O_>>>(fc_w, fc_b, (float*)d_out);
}

// round 8
// speedup vs baseline: 1.2339x; 1.2339x over previous
#include <cuda_runtime.h>
#include <cuda_fp16.h>
#include <cstdint>

#define B_   64
#define T_   512
#define H_   1024
#define L_   4
#define O_   256
#define NCTA 128
#define NTHR 256

#define KC      128                       // K per chunk
#define NCHUNK  16                        // 2048 / 128
#define WSTG    32768                     // W tile 128 rows x 256B
#define ASTG    16384                     // A tile  64 rows x 256B
#define STG     (WSTG + ASTG)             // 49152 per stage
#define OFF_SG  (3 * STG)                 // 147456 : gate preacts 64x128 f32
#define OFF_SC  (OFF_SG + 64 * 128 * 4)   // 180224 : cell state 64x32 f32
#define SMEM_TOTAL (OFF_SC + 8192)        // 188416

// XOR-swizzled index into sG: m in [0,64), n in [0,128). 2-way-optimal for
// float2 epilogue stores, conflict-free for per-lane cell reads.
#define SGIDX(m, n) (((m) << 7) + ((n) ^ (((m) & 3) << 3)))

// ---------------- scratch (static device globals; no allocation) ----------------
__device__ __half g_Wc[(size_t)L_ * 32 * 128 * 2048];  // [l][s][j=128][k=2048] fp16
__device__ __half g_x[(size_t)T_ * B_ * H_];           // x fp16, [t][b][d]
__device__ __half g_h[2 * L_ * B_ * H_];               // h fp16, [parity][l][b][h]
__device__ float  g_bias[L_ * 4 * H_];                 // bih + bhh
__device__ float  g_h3[B_ * H_];                       // final layer-3 h (fp32)
__device__ unsigned g_barGen;
__device__ unsigned g_barCnt;

// ---------------- helpers --------------------------------------------------------
__device__ __forceinline__ uint32_t smem_u32(const void* p) {
    uint32_t a;
    asm("{ .reg .u64 t; cvta.to.shared.u64 t, %1; cvt.u32.u64 %0, t; }" : "=r"(a) : "l"(p));
    return a;
}
__device__ __forceinline__ void cpa16(uint32_t dst, const void* src) {
    asm volatile("cp.async.cg.shared.global [%0], [%1], 16;" :: "r"(dst), "l"(src) : "memory");
}
__device__ __forceinline__ void cp_commit() {
    asm volatile("cp.async.commit_group;" ::: "memory");
}
__device__ __forceinline__ void cp_wait1() {
    asm volatile("cp.async.wait_group 1;" ::: "memory");
}
__device__ __forceinline__ void ldsm4(uint32_t* r, uint32_t a) {
    asm volatile("ldmatrix.sync.aligned.m8n8.x4.shared.b16 {%0,%1,%2,%3}, [%4];"
                 : "=r"(r[0]), "=r"(r[1]), "=r"(r[2]), "=r"(r[3]) : "r"(a));
}
__device__ __forceinline__ void mma16816(float* c, const uint32_t* a, const uint32_t* b) {
    asm volatile(
        "mma.sync.aligned.m16n8k16.row.col.f32.f16.f16.f32 "
        "{%0,%1,%2,%3}, {%4,%5,%6,%7}, {%8,%9}, {%0,%1,%2,%3};\n"
        : "+f"(c[0]), "+f"(c[1]), "+f"(c[2]), "+f"(c[3])
        : "r"(a[0]), "r"(a[1]), "r"(a[2]), "r"(a[3]), "r"(b[0]), "r"(b[1]));
}

// ---------------- split grid barrier (128 CTAs, 1/SM, all resident) --------------
// arrive returns the generation (valid on tid 0 only); wait polls it.
__device__ __forceinline__ unsigned bar_arrive() {
    __threadfence();
    __syncthreads();
    unsigned gen = 0;
    if (threadIdx.x == 0) {
        gen = *((volatile unsigned*)&g_barGen);
        __threadfence();
        unsigned prev = atomicAdd(&g_barCnt, 1u);
        if (prev == NCTA - 1) {
            g_barCnt = 0;
            __threadfence();
            atomicAdd(&g_barGen, 1u);
        }
    }
    return gen;
}
__device__ __forceinline__ void bar_wait(unsigned gen) {
    if (threadIdx.x == 0) {
        while (*((volatile unsigned*)&g_barGen) == gen) { }
    }
    __syncthreads();
}

// ---------------- prep: weight swizzle + x fp16 + fused bias ---------------------
__global__ void prep_kernel(const float* __restrict__ x,
                            const float* __restrict__ Wih,
                            const float* __restrict__ Whh,
                            const float* __restrict__ bih,
                            const float* __restrict__ bhh) {
    long long tid = (long long)blockIdx.x * blockDim.x + threadIdx.x;
    long long stride = (long long)gridDim.x * blockDim.x;

    const long long NW = (long long)L_ * 32 * 128 * 2048;
    for (long long n = tid; n < NW; n += stride) {
        int k = (int)(n & 2047);
        int j = (int)((n >> 11) & 127);
        int s = (int)((n >> 18) & 31);
        int l = (int)(n >> 23);
        int g = j >> 5, jj = j & 31;
        int row = g * 1024 + s * 32 + jj;
        float v = (k < 1024)
            ? Wih[((long long)l * 4096 + row) * 1024 + k]
            : Whh[((long long)l * 4096 + row) * 1024 + (k - 1024)];
        g_Wc[n] = __float2half_rn(v);
    }

    const long long NX = (long long)T_ * B_ * H_;
    for (long long n = tid; n < NX; n += stride) {
        int d = (int)(n & 1023);
        int b = (int)((n >> 10) & 63);
        int t = (int)(n >> 16);
        g_x[n] = __float2half_rn(x[((long long)b * T_ + t) * H_ + d]);
    }

    for (long long n = tid; n < L_ * 4 * H_; n += stride)
        g_bias[n] = bih[n] + bhh[n];
}

// ---------------- persistent LSTM kernel -----------------------------------------
__global__ void __launch_bounds__(NTHR, 1) lstm_kernel() {
    extern __shared__ __align__(1024) char smem[];
    const uint32_t sb = smem_u32(smem);
    const int tid = threadIdx.x;
    const int lane = tid & 31;
    const int wid = tid >> 5;
    const int bid = blockIdx.x;
    const int l = bid >> 5;          // layer
    const int s = bid & 31;          // gate-column slice (32 h cols)

    float* sG = (float*)(smem + OFF_SG);  // [b=64][n=128] XOR-swizzled
    float* sC = (float*)(smem + OFF_SC);  // [b=64][hc=32]

    // zero h double buffer + c state
    {
        const int total = (2 * L_ * B_ * H_) / 8;     // uint4 count
        uint4 z = make_uint4(0, 0, 0, 0);
        for (int i = bid * NTHR + tid; i < total; i += NCTA * NTHR)
            ((uint4*)g_h)[i] = z;
        for (int i = tid; i < B_ * 32; i += NTHR) sC[i] = 0.f;
    }

    // elementwise constants
    const int hcl = tid & 31;
    const int eb0 = tid >> 5;
    float bias_g[4];
    #pragma unroll
    for (int g = 0; g < 4; ++g)
        bias_g[g] = g_bias[l * 4096 + g * 1024 + s * 32 + hcl];

    // warp / lane tiling for mma (R6: 2x4 grid of 32x32 tiles — LDSM-minimal)
    const int wm = wid >> 2;              // 0..1 : batch rows  [wm*32, +32)
    const int wn = wid & 3;               // 0..3 : gate rows   [wn*32, +32)
    const int t8 = lane >> 3;
    const int r8 = lane & 7;
    const uint32_t swz = (uint32_t)r8;
    const uint32_t tA = (uint32_t)(t8 >> 1);
    const uint32_t tB = (uint32_t)(t8 & 1);

    uint32_t aBase[3][2], bBase[3][2];
    #pragma unroll
    for (int st = 0; st < 3; ++st) {
        uint32_t wa = sb + st * STG;
        #pragma unroll
        for (int mi = 0; mi < 2; ++mi) {
            int m = wm * 32 + mi * 16 + (t8 & 1) * 8 + r8;
            aBase[st][mi] = wa + WSTG + m * 256;
        }
        #pragma unroll
        for (int p = 0; p < 2; ++p) {
            int n = wn * 32 + p * 16 + (t8 >> 1) * 8 + r8;
            bBase[st][p] = wa + n * 256;
        }
    }

    const __half* Wbase = g_Wc + (size_t)(l * 32 + s) * 128 * 2048;

    // W-part staging (tick-invariant source — safe to prefetch across barriers)
    auto issueW = [&](int kc, int st) {
        const __half* Wsrc = Wbase + kc * KC;
        uint32_t wdst = sb + st * STG;
        #pragma unroll
        for (int q = 0; q < 8; ++q) {
            int f = tid + q * 256;
            int j = f >> 4, c16 = f & 15;
            uint32_t d = wdst + (uint32_t)(j * 256) + ((uint32_t)(c16 ^ (j & 7)) << 4);
            cpa16(d, Wsrc + (size_t)j * 2048 + c16 * 8);
        }
    };

    // ---- initial barrier + first-tick W prefetch ----
    unsigned gen = bar_arrive();
    if (l == 0) { issueW(0, 0); issueW(1, 1); }   // tau=0 active only for layer 0
    bar_wait(gen);

    for (int tau = 0; tau < T_ + L_ - 1; ++tau) {
        const int t = tau - l;
        if (t >= 0 && t < T_) {
            const int par = tau & 1;
            const __half* hin = g_h + (par ^ 1) * (L_ * B_ * H_);
            const __half* in  = (l == 0) ? (g_x + (size_t)t * (B_ * H_))
                                         : (hin + (l - 1) * (B_ * H_));
            const __half* rec = hin + l * (B_ * H_);

            auto issueA = [&](int kc, int st) {
                const __half* Asrc = (kc < 8) ? in : rec;
                const int kloc = (kc & 7) * KC;
                uint32_t adst = sb + st * STG + WSTG;
                #pragma unroll
                for (int q = 0; q < 4; ++q) {
                    int f = tid + q * 256;
                    int b = f >> 4, c16 = f & 15;
                    uint32_t d = adst + (uint32_t)(b * 256) + ((uint32_t)(c16 ^ (b & 7)) << 4);
                    cpa16(d, Asrc + (size_t)b * 1024 + kloc + c16 * 8);
                }
            };

            float acc[2][4][4];
            #pragma unroll
            for (int mi = 0; mi < 2; ++mi)
                #pragma unroll
                for (int ni = 0; ni < 4; ++ni)
                    #pragma unroll
                    for (int q = 0; q < 4; ++q) acc[mi][ni][q] = 0.f;

            // W0/W1 already in flight (issued at the barrier). Add A parts.
            issueA(0, 0); cp_commit();      // group = {W0, W1, A0}
            issueA(1, 1); cp_commit();      // group = {A1}

            #pragma unroll
            for (int kc = 0; kc < NCHUNK; ++kc) {
                const int st = kc % 3;
                cp_wait1();            // chunk kc resident (this thread)
                __syncthreads();       // all threads' chunk kc resident; st reusable
                if (kc + 2 < NCHUNK) { issueW(kc + 2, (kc + 2) % 3); issueA(kc + 2, (kc + 2) % 3); }
                cp_commit();           // (possibly empty) keeps group counts aligned

                #pragma unroll
                for (int kk = 0; kk < 8; ++kk) {
                    uint32_t a[2][4], bf[2][4];
                    #pragma unroll
                    for (int mi = 0; mi < 2; ++mi)
                        ldsm4(a[mi], aBase[st][mi] + ((((uint32_t)(2 * kk) + tA) ^ swz) << 4));
                    #pragma unroll
                    for (int p = 0; p < 2; ++p)
                        ldsm4(bf[p], bBase[st][p] + ((((uint32_t)(2 * kk) + tB) ^ swz) << 4));
                    #pragma unroll
                    for (int mi = 0; mi < 2; ++mi)
                        #pragma unroll
                        for (int p = 0; p < 2; ++p) {
                            mma16816(acc[mi][2 * p],     a[mi], &bf[p][0]);
                            mma16816(acc[mi][2 * p + 1], a[mi], &bf[p][2]);
                        }
                }
            }

            // ---- epilogue: acc -> sG[b][n] (swizzled; 2-way conflicts max) ----
            {
                const int grp = lane >> 2, tg = lane & 3;
                #pragma unroll
                for (int mi = 0; mi < 2; ++mi)
                    #pragma unroll
                    for (int ni = 0; ni < 4; ++ni) {
                        int n = wn * 32 + ni * 8 + tg * 2;
                        int m0 = wm * 32 + mi * 16 + grp;
                        *(float2*)&sG[SGIDX(m0, n)]     = make_float2(acc[mi][ni][0], acc[mi][ni][1]);
                        *(float2*)&sG[SGIDX(m0 + 8, n)] = make_float2(acc[mi][ni][2], acc[mi][ni][3]);
                    }
            }
            __syncthreads();

            // ---- elementwise LSTM cell ----
            __half* hout = g_h + par * (L_ * B_ * H_) + l * (B_ * H_);
            #pragma unroll
            for (int b = eb0; b < 64; b += 8) {
                float ai = sG[SGIDX(b, 0 * 32 + hcl)] + bias_g[0];
                float af = sG[SGIDX(b, 1 * 32 + hcl)] + bias_g[1];
                float ag = sG[SGIDX(b, 2 * 32 + hcl)] + bias_g[2];
                float ao = sG[SGIDX(b, 3 * 32 + hcl)] + bias_g[3];
                float ig = 1.f / (1.f + __expf(-ai));
                float fg = 1.f / (1.f + __expf(-af));
                float gg = tanhf(ag);
                float og = 1.f / (1.f + __expf(-ao));
                float cs = fg * sC[b * 32 + hcl] + ig * gg;
                sC[b * 32 + hcl] = cs;
                float hv = og * tanhf(cs);
                int go = b * 1024 + s * 32 + hcl;
                __stcg(hout + go, __float2half_rn(hv));
                if (l == 3 && t == T_ - 1) g_h3[go] = hv;
            }
        }

        // ---- barrier with next-tick W prefetch hidden in the arrive/wait gap ----
        gen = bar_arrive();
        const int t2 = tau + 1 - l;
        if (t2 >= 0 && t2 < T_) { issueW(0, 0); issueW(1, 1); }
        bar_wait(gen);
    }
}

// ---------------- final FC: out[b][o] = h3[b] . fc_w[o] + fc_b[o] ----------------
__global__ void fc_kernel(const float* __restrict__ fc_w,
                          const float* __restrict__ fc_b,
                          float* __restrict__ out) {
    __shared__ float hs[H_];
    const int b = blockIdx.x;
    const int o = threadIdx.x;
    for (int k = o; k < H_; k += O_) hs[k] = g_h3[b * H_ + k];
    __syncthreads();
    const float* w = fc_w + (long long)o * H_;
    float a0 = 0.f, a1 = 0.f, a2 = 0.f, a3 = 0.f;
    #pragma unroll 4
    for (int k = 0; k < H_; k += 4) {
        a0 += hs[k + 0] * __ldg(w + k + 0);
        a1 += hs[k + 1] * __ldg(w + k + 1);
        a2 += hs[k + 2] * __ldg(w + k + 2);
        a3 += hs[k + 3] * __ldg(w + k + 3);
    }
    out[b * O_ + o] = fc_b[o] + ((a0 + a1) + (a2 + a3));
}

// ---------------- launch ----------------------------------------------------------
extern "C" void kernel_launch(void* const* d_in, const int* in_sizes, int n_in,
                              void* d_out, int out_size) {
    (void)in_sizes; (void)n_in; (void)out_size;
    const float* x    = (const float*)d_in[0];
    const float* Wih  = (const float*)d_in[1];
    const float* Whh  = (const float*)d_in[2];
    const float* bih  = (const float*)d_in[3];
    const float* bhh  = (const float*)d_in[4];
    const float* fc_w = (const float*)d_in[5];
    const float* fc_b = (const float*)d_in[6];

    cudaFuncSetAttribute(lstm_kernel, cudaFuncAttributeMaxDynamicSharedMemorySize, SMEM_TOTAL);
    prep_kernel<<<2048, 256>>>(x, Wih, Whh, bih, bhh);
    lstm_kernel<<<NCTA, NTHR, SMEM_TOTAL>>>();
    fc_kernel<<<B_, O_>>>(fc_w, fc_b, (float*)d_out);
}